// round 2
// baseline (speedup 1.0000x reference)
#include <cuda_runtime.h>

#define DIMC 192
#define RR   48          // DIM / RED
#define BB   4
#define HH   256
#define WW   256
#define HW   (HH * WW)   // 65536
#define KK   3
#define NWT  (DIMC * KK * KK)   // 1728
#define EPSV 1e-5f

// Scratch (no allocations allowed)
__device__ float g_pooled[BB * DIMC];        // 768
__device__ float g_wt[BB * DIMC * 4];        // 4 live taps per (b,c)

// ---------------------------------------------------------------------------
// Kernel 1: global average pool per (b,c). One block per channel.
// ---------------------------------------------------------------------------
__global__ void __launch_bounds__(256) pool_kernel(const float* __restrict__ x) {
    const int bc  = blockIdx.x;                 // 0..767
    const float4* p = (const float4*)(x + (size_t)bc * HW);
    const int n4 = HW / 4;                      // 16384
    float s = 0.f;
    for (int i = threadIdx.x; i < n4; i += 256) {
        float4 v = p[i];
        s += (v.x + v.y) + (v.z + v.w);
    }
    // warp reduce
    #pragma unroll
    for (int o = 16; o > 0; o >>= 1) s += __shfl_xor_sync(0xffffffffu, s, o);
    __shared__ float sm[8];
    if ((threadIdx.x & 31) == 0) sm[threadIdx.x >> 5] = s;
    __syncthreads();
    if (threadIdx.x == 0) {
        float t = 0.f;
        #pragma unroll
        for (int i = 0; i < 8; i++) t += sm[i];
        g_pooled[bc] = t * (1.0f / (float)HW);
    }
}

// ---------------------------------------------------------------------------
// Kernel 2: weight generation MLP (tiny). Single block of 256 threads.
//   t = relu(BN(pooled @ w1^T)); wt = t @ w2^T + b2; apply mask -> 4 taps.
// ---------------------------------------------------------------------------
__global__ void __launch_bounds__(256) wgen_kernel(
    const float* __restrict__ w1,
    const float* __restrict__ gamma, const float* __restrict__ beta,
    const float* __restrict__ rmean, const float* __restrict__ rvar,
    const float* __restrict__ w2,   const float* __restrict__ b2)
{
    __shared__ float s_t[BB * RR];              // 192
    const int tid = threadIdx.x;

    if (tid < BB * RR) {
        const int b = tid / RR;
        const int j = tid % RR;
        const float* pl = g_pooled + b * DIMC;
        const float* wr = w1 + j * DIMC;
        float acc = 0.f;
        #pragma unroll 4
        for (int c = 0; c < DIMC; c++) acc = fmaf(pl[c], wr[c], acc);
        float v = gamma[j] * (acc - rmean[j]) * rsqrtf(rvar[j] + EPSV) + beta[j];
        s_t[tid] = fmaxf(v, 0.f);
    }
    __syncthreads();

    // Only the 4 unmasked taps (tap 0..3 of the 3x3) are ever nonzero.
    // kept index layout: idx = b*768 + c*4 + tap ; o = c*9 + tap
    const int NKEPT = BB * DIMC * 4;            // 3072
    for (int idx = tid; idx < NKEPT; idx += 256) {
        const int b   = idx / (DIMC * 4);
        const int rem = idx % (DIMC * 4);
        const int c   = rem >> 2;
        const int tap = rem & 3;
        const int o   = c * 9 + tap;
        const float* tv = s_t + b * RR;
        const float* wr = w2 + o * RR;
        float acc = b2[o];
        #pragma unroll
        for (int j = 0; j < RR; j++) acc = fmaf(tv[j], wr[j], acc);
        g_wt[idx] = acc;
    }
}

// ---------------------------------------------------------------------------
// Kernel 3: 4-tap masked depthwise stencil + bias.
//   out[y][x] = w0*in[y-1][x-1] + w1*in[y-1][x] + w2*in[y-1][x+1]
//             + w3*in[y][x-1]   + bias[c]
// Block (64,4): 4 rows of one channel; thread = 4 consecutive pixels (float4).
// grid = (H/4, B*DIM)
// ---------------------------------------------------------------------------
__global__ void __launch_bounds__(256) conv_kernel(
    const float* __restrict__ x, const float* __restrict__ bias,
    float* __restrict__ out)
{
    const int bc = blockIdx.y;                  // 0..767
    const int c  = bc % DIMC;
    const int y  = blockIdx.x * 4 + threadIdx.y;
    const int x4 = threadIdx.x * 4;

    const float w0 = g_wt[bc * 4 + 0];
    const float w1 = g_wt[bc * 4 + 1];
    const float w2 = g_wt[bc * 4 + 2];
    const float w3 = g_wt[bc * 4 + 3];
    const float bv = bias[c];

    const float* in  = x + (size_t)bc * HW;
    const float* cur = in + (size_t)y * WW;

    // previous row, indices x4-1 .. x4+4
    float p0, p1, p2, p3, p4, p5;
    if (y > 0) {
        const float* prv = cur - WW;
        float4 v = *(const float4*)(prv + x4);
        p1 = v.x; p2 = v.y; p3 = v.z; p4 = v.w;
        p0 = (x4 > 0)        ? prv[x4 - 1] : 0.f;
        p5 = (x4 + 4 < WW)   ? prv[x4 + 4] : 0.f;
    } else {
        p0 = p1 = p2 = p3 = p4 = p5 = 0.f;
    }

    float4 cv = *(const float4*)(cur + x4);
    float cm1 = (x4 > 0) ? cur[x4 - 1] : 0.f;

    float4 o;
    o.x = fmaf(w0, p0, fmaf(w1, p1, fmaf(w2, p2, fmaf(w3, cm1,  bv))));
    o.y = fmaf(w0, p1, fmaf(w1, p2, fmaf(w2, p3, fmaf(w3, cv.x, bv))));
    o.z = fmaf(w0, p2, fmaf(w1, p3, fmaf(w2, p4, fmaf(w3, cv.y, bv))));
    o.w = fmaf(w0, p3, fmaf(w1, p4, fmaf(w2, p5, fmaf(w3, cv.z, bv))));

    *(float4*)(out + (size_t)bc * HW + (size_t)y * WW + x4) = o;
}

// ---------------------------------------------------------------------------
extern "C" void kernel_launch(void* const* d_in, const int* in_sizes, int n_in,
                              void* d_out, int out_size)
{
    const float* x     = (const float*)d_in[0];
    const float* w1    = (const float*)d_in[1];
    const float* gamma = (const float*)d_in[2];
    const float* beta  = (const float*)d_in[3];
    const float* rmean = (const float*)d_in[4];
    const float* rvar  = (const float*)d_in[5];
    const float* w2    = (const float*)d_in[6];
    const float* b2    = (const float*)d_in[7];
    const float* bias  = (const float*)d_in[8];
    float* out = (float*)d_out;

    pool_kernel<<<BB * DIMC, 256>>>(x);
    wgen_kernel<<<1, 256>>>(w1, gamma, beta, rmean, rvar, w2, b2);
    dim3 blk(64, 4);
    dim3 grd(HH / 4, BB * DIMC);
    conv_kernel<<<grd, blk>>>(x, bias, out);
}